// round 2
// baseline (speedup 1.0000x reference)
#include <cuda_runtime.h>

// network_5299989643808: per-(z,zp)-pair tiny MLP over batch B.
//   x = (nt[b,z], nt[b,zp])  ->  4-dim hidden x2 (tanh+LayerNorm)  ->
//   pi = softmax head (4), log_pi, xi = sigmoid head (4)
// Inputs (metadata order): nt, W1, b1, g1, be1, W2, b2, g2, be2, Wpi, bpi, Wxi, bxi
// Output: concat(pi, log_pi, xi), each [B, 64, 64, 4] fp32.

static constexpr int ZZ  = 64;   // zones
static constexpr int BCH = 64;   // batch elements per block (y-dim chunk)

__device__ __forceinline__ float fast_rsqrt(float x) {
    float r; asm("rsqrt.approx.f32 %0, %1;" : "=f"(r) : "f"(x)); return r;
}
__device__ __forceinline__ float fast_rcp(float x) {
    float r; asm("rcp.approx.f32 %0, %1;" : "=f"(r) : "f"(x)); return r;
}
// Exact identity tanh(x) = 1 - 2/(1+exp(2x)); robust at +/-inf, ~1e-7 error.
__device__ __forceinline__ float fast_tanh(float x) {
    float e = __expf(2.0f * x);
    return 1.0f - 2.0f * fast_rcp(e + 1.0f);
}
// Streaming 128-bit store (evict-first: output is write-once, never re-read).
__device__ __forceinline__ void store_cs(float4* p, float4 v) {
    asm volatile("st.global.cs.v4.f32 [%0], {%1, %2, %3, %4};"
                 :: "l"(p), "f"(v.x), "f"(v.y), "f"(v.z), "f"(v.w) : "memory");
}

__global__ __launch_bounds__(128, 4)
void mlp_pairs_kernel(
    const float* __restrict__ nt,
    const float* __restrict__ W1,  const float* __restrict__ b1,
    const float* __restrict__ g1,  const float* __restrict__ be1,
    const float* __restrict__ W2,  const float* __restrict__ b2,
    const float* __restrict__ g2,  const float* __restrict__ be2,
    const float* __restrict__ Wpi, const float* __restrict__ bpi,
    const float* __restrict__ Wxi, const float* __restrict__ bxi,
    float* __restrict__ out, int nB)
{
    const int p  = blockIdx.x * blockDim.x + threadIdx.x;  // pair index 0..4095
    const int z  = p >> 6;
    const int zp = p & 63;

    // ---- Load weights for this pair, folding LN gamma/beta into next layer ----
    const float4* W1v = reinterpret_cast<const float4*>(W1) + (size_t)p * 2;
    float4 w1a = W1v[0];                                   // input 0 -> h0..h3
    float4 w1b = W1v[1];                                   // input 1 -> h0..h3
    float4 b1v = reinterpret_cast<const float4*>(b1)[p];
    float4 g1v = reinterpret_cast<const float4*>(g1)[p];
    float4 e1v = reinterpret_cast<const float4*>(be1)[p];
    float4 g2v = reinterpret_cast<const float4*>(g2)[p];
    float4 e2v = reinterpret_cast<const float4*>(be2)[p];

    const float g1a[4] = {g1v.x, g1v.y, g1v.z, g1v.w};
    const float e1a[4] = {e1v.x, e1v.y, e1v.z, e1v.w};
    const float g2a[4] = {g2v.x, g2v.y, g2v.z, g2v.w};
    const float e2a[4] = {e2v.x, e2v.y, e2v.z, e2v.w};

    // W2 folded: W2f[i][k] = W2[i][k]*g1[i];  b2f[k] = b2[k] + sum_i be1[i]*W2[i][k]
    float W2f[16], b2f[4];
    {
        float4 b2v = reinterpret_cast<const float4*>(b2)[p];
        b2f[0] = b2v.x; b2f[1] = b2v.y; b2f[2] = b2v.z; b2f[3] = b2v.w;
        const float4* W2v = reinterpret_cast<const float4*>(W2) + (size_t)p * 4;
        #pragma unroll
        for (int i = 0; i < 4; ++i) {
            float4 row = W2v[i];
            float rr[4] = {row.x, row.y, row.z, row.w};
            #pragma unroll
            for (int k = 0; k < 4; ++k) {
                W2f[i * 4 + k] = rr[k] * g1a[i];
                b2f[k] = fmaf(e1a[i], rr[k], b2f[k]);
            }
        }
    }
    // Heads folded with g2/be2
    float Wpf[16], bpf[4], Wxf[16], bxf[4];
    {
        float4 bpv = reinterpret_cast<const float4*>(bpi)[p];
        float4 bxv = reinterpret_cast<const float4*>(bxi)[p];
        bpf[0] = bpv.x; bpf[1] = bpv.y; bpf[2] = bpv.z; bpf[3] = bpv.w;
        bxf[0] = bxv.x; bxf[1] = bxv.y; bxf[2] = bxv.z; bxf[3] = bxv.w;
        const float4* Wpv = reinterpret_cast<const float4*>(Wpi) + (size_t)p * 4;
        const float4* Wxv = reinterpret_cast<const float4*>(Wxi) + (size_t)p * 4;
        #pragma unroll
        for (int k = 0; k < 4; ++k) {
            float4 rp = Wpv[k];
            float rpa[4] = {rp.x, rp.y, rp.z, rp.w};
            float4 rx = Wxv[k];
            float rxa[4] = {rx.x, rx.y, rx.z, rx.w};
            #pragma unroll
            for (int o = 0; o < 4; ++o) {
                Wpf[k * 4 + o] = rpa[o] * g2a[k];
                bpf[o] = fmaf(e2a[k], rpa[o], bpf[o]);
                Wxf[k * 4 + o] = rxa[o] * g2a[k];
                bxf[o] = fmaf(e2a[k], rxa[o], bxf[o]);
            }
        }
    }

    const float w1x[4] = {w1a.x, w1a.y, w1a.z, w1a.w};
    const float w1y[4] = {w1b.x, w1b.y, w1b.z, w1b.w};
    const float b1a[4] = {b1v.x, b1v.y, b1v.z, b1v.w};

    const size_t N4 = (size_t)nB * ZZ * ZZ;               // float4 count per tensor
    float4* __restrict__ outPi = reinterpret_cast<float4*>(out);
    float4* __restrict__ outLp = outPi + N4;
    float4* __restrict__ outXi = outPi + 2 * N4;

    const int b0   = blockIdx.y * BCH;
    const int bend = (b0 + BCH < nB) ? (b0 + BCH) : nB;

    const float* ntz  = nt + z;
    const float* ntzp = nt + zp;

    for (int b = b0; b < bend; ++b) {
        const float x0 = __ldg(ntz  + (size_t)b * ZZ);
        const float x1 = __ldg(ntzp + (size_t)b * ZZ);

        // layer 1: tanh(W1^T x + b1)
        float h[4];
        #pragma unroll
        for (int i = 0; i < 4; ++i)
            h[i] = fast_tanh(fmaf(w1x[i], x0, fmaf(w1y[i], x1, b1a[i])));

        // LN1 (gamma/beta folded into layer 2)
        {
            float m = (h[0] + h[1] + h[2] + h[3]) * 0.25f;
            float v = 0.0f;
            #pragma unroll
            for (int i = 0; i < 4; ++i) { h[i] -= m; v = fmaf(h[i], h[i], v); }
            float r = fast_rsqrt(fmaf(v, 0.25f, 1e-5f));
            #pragma unroll
            for (int i = 0; i < 4; ++i) h[i] *= r;
        }

        // layer 2: tanh(W2f^T h + b2f)
        float h2[4];
        #pragma unroll
        for (int k = 0; k < 4; ++k) {
            float pre = b2f[k];
            #pragma unroll
            for (int i = 0; i < 4; ++i) pre = fmaf(h[i], W2f[i * 4 + k], pre);
            h2[k] = fast_tanh(pre);
        }

        // LN2 (gamma/beta folded into heads)
        {
            float m = (h2[0] + h2[1] + h2[2] + h2[3]) * 0.25f;
            float v = 0.0f;
            #pragma unroll
            for (int k = 0; k < 4; ++k) { h2[k] -= m; v = fmaf(h2[k], h2[k], v); }
            float r = fast_rsqrt(fmaf(v, 0.25f, 1e-5f));
            #pragma unroll
            for (int k = 0; k < 4; ++k) h2[k] *= r;
        }

        // heads
        float pl[4], xl[4];
        #pragma unroll
        for (int o = 0; o < 4; ++o) { pl[o] = bpf[o]; xl[o] = bxf[o]; }
        #pragma unroll
        for (int k = 0; k < 4; ++k) {
            #pragma unroll
            for (int o = 0; o < 4; ++o) {
                pl[o] = fmaf(h2[k], Wpf[k * 4 + o], pl[o]);
                xl[o] = fmaf(h2[k], Wxf[k * 4 + o], xl[o]);
            }
        }

        // stable log-softmax + softmax
        float mx = fmaxf(fmaxf(pl[0], pl[1]), fmaxf(pl[2], pl[3]));
        float e[4], s = 0.0f;
        #pragma unroll
        for (int o = 0; o < 4; ++o) { pl[o] -= mx; e[o] = __expf(pl[o]); s += e[o]; }
        float inv = fast_rcp(s);
        float ls  = __logf(s);

        float4 piv = make_float4(e[0] * inv, e[1] * inv, e[2] * inv, e[3] * inv);
        float4 lpv = make_float4(pl[0] - ls, pl[1] - ls, pl[2] - ls, pl[3] - ls);

        // sigmoid head
        float xi[4];
        #pragma unroll
        for (int o = 0; o < 4; ++o)
            xi[o] = fast_rcp(1.0f + __expf(-xl[o]));
        float4 xiv = make_float4(xi[0], xi[1], xi[2], xi[3]);

        const size_t base = ((size_t)b * ZZ + z) * ZZ + zp;
        store_cs(outPi + base, piv);
        store_cs(outLp + base, lpv);
        store_cs(outXi + base, xiv);
    }
}

extern "C" void kernel_launch(void* const* d_in, const int* in_sizes, int n_in,
                              void* d_out, int out_size)
{
    const float* nt  = (const float*)d_in[0];
    const float* W1  = (const float*)d_in[1];
    const float* b1  = (const float*)d_in[2];
    const float* g1  = (const float*)d_in[3];
    const float* be1 = (const float*)d_in[4];
    const float* W2  = (const float*)d_in[5];
    const float* b2  = (const float*)d_in[6];
    const float* g2  = (const float*)d_in[7];
    const float* be2 = (const float*)d_in[8];
    const float* Wpi = (const float*)d_in[9];
    const float* bpi = (const float*)d_in[10];
    const float* Wxi = (const float*)d_in[11];
    const float* bxi = (const float*)d_in[12];
    float* out = (float*)d_out;

    const int nB = in_sizes[0] / ZZ;   // 2048

    dim3 block(128);
    dim3 grid((ZZ * ZZ) / 128, (nB + BCH - 1) / BCH);
    mlp_pairs_kernel<<<grid, block>>>(nt, W1, b1, g1, be1, W2, b2, g2, be2,
                                      Wpi, bpi, Wxi, bxi, out, nB);
}